// round 3
// baseline (speedup 1.0000x reference)
#include <cuda_runtime.h>
#include <math.h>

#define NN 50000
#define EE 1600000
#define TT 12
#define FF 16
#define HH 128
#define OUTD 3
#define HOR 6

// ---------------- scratch (static device globals; no allocation) ----------------
__device__ float g_dinv_all[TT * NN];
__device__ int   g_cnt[TT * NN];
__device__ int   g_rowstart[TT * (NN + 1)];
__device__ int   g_cursor[TT * NN];
__device__ int2  g_csr[TT * EE];            // (src, nrm bits)
__device__ float g_agg_all[(size_t)TT * NN * FF];
__device__ float g_aggh[NN * FF];           // horizon gather output
__device__ float g_z[NN * HH];
__device__ float g_hr[NN * HH];
__device__ float g_h[NN * HH];
__device__ float g_hw[NN * HH];
__device__ float g_xmod[NN * FF];
__device__ unsigned char g_maskc[TT * NN];
__device__ unsigned char g_meff[TT * NN];   // mask[t] & (mask[0]|...|mask[t-1])
__device__ float g_Bzr_top[16 * 256];
__device__ float g_bzr[256];
__device__ float g_Bzr_bot[128 * 256];
__device__ float g_Bh_top[16 * 128];
__device__ float g_bh[128];
__device__ int g_isbyte;

// ---------------- f32x2 packed-FMA helpers ----------------
__device__ __forceinline__ unsigned long long pack2(float lo, float hi) {
    unsigned long long r;
    asm("mov.b64 %0, {%1, %2};" : "=l"(r) : "f"(lo), "f"(hi));
    return r;
}
__device__ __forceinline__ void fma2(unsigned long long& acc,
                                     unsigned long long a, unsigned long long b) {
    asm("fma.rn.f32x2 %0, %1, %2, %0;" : "+l"(acc) : "l"(a), "l"(b));
}
__device__ __forceinline__ float2 unpack2(unsigned long long v) {
    float2 f;
    asm("mov.b64 {%0, %1}, %2;" : "=f"(f.x), "=f"(f.y) : "l"(v));
    return f;
}

// ---------------- mask dtype detection + canonicalization ----------------
__global__ void k_detect(const unsigned char* raw) {
    __shared__ int cnt;
    if (threadIdx.x == 0) cnt = 0;
    __syncthreads();
    int c = 0;
    for (int i = threadIdx.x; i < 4096; i += blockDim.x)
        c += (raw[i] != 0);
    atomicAdd(&cnt, c);
    __syncthreads();
    if (threadIdx.x == 0) g_isbyte = (cnt > 2048) ? 1 : 0;
}

__global__ void k_convert(const unsigned char* raw) {
    int n = blockIdx.x * blockDim.x + threadIdx.x;
    if (n >= NN) return;
    int isb = g_isbyte;
    int seen = 0;
#pragma unroll
    for (int t = 0; t < TT; ++t) {
        int m = isb ? (raw[t * NN + n] != 0)
                    : (((const int*)raw)[t * NN + n] != 0);
        g_maskc[t * NN + n] = (unsigned char)m;
        g_meff[t * NN + n] = (unsigned char)(m & seen);
        seen |= m;
    }
}

// ---------------- weight fusion ----------------
__global__ void k_fuse(const float* __restrict__ Wcz, const float* __restrict__ Wlz,
                       const float* __restrict__ blz, const float* __restrict__ bcz,
                       const float* __restrict__ Wcr, const float* __restrict__ Wlr,
                       const float* __restrict__ blr, const float* __restrict__ bcr,
                       const float* __restrict__ Wch, const float* __restrict__ Wlh,
                       const float* __restrict__ blh, const float* __restrict__ bch) {
    int i = blockIdx.x * blockDim.x + threadIdx.x;
    if (i < 16 * 256) {                           // Bzr_top
        int k = i / 256, c = i % 256, cc = c & 127;
        const float* A = (c < 128) ? Wcz : Wcr;
        const float* B = (c < 128) ? Wlz : Wlr;
        float s = 0.f;
        for (int j = 0; j < 128; ++j) s += A[k * 128 + j] * B[j * 128 + cc];
        g_Bzr_top[i] = s;
    } else if (i < 4096 + 2048) {                 // Bh_top
        int r = i - 4096; int k = r / 128, c = r % 128;
        float s = 0.f;
        for (int j = 0; j < 128; ++j) s += Wch[k * 128 + j] * Wlh[j * 128 + c];
        g_Bh_top[r] = s;
    } else if (i < 6144 + 256) {                  // fused z|r bias
        int c = i - 6144; int cc = c & 127;
        const float* bc = (c < 128) ? bcz : bcr;
        const float* B  = (c < 128) ? Wlz : Wlr;
        const float* bl = (c < 128) ? blz : blr;
        float s = bl[cc];
        for (int j = 0; j < 128; ++j) s += bc[j] * B[j * 128 + cc];
        g_bzr[c] = s;
    } else if (i < 6400 + 128) {                  // fused h bias
        int c = i - 6400;
        float s = blh[c];
        for (int j = 0; j < 128; ++j) s += bch[j] * Wlh[j * 128 + c];
        g_bh[c] = s;
    } else if (i < 6528 + 128 * 256) {            // Bzr_bot pack
        int r = i - 6528; int k = r / 256, c = r % 256;
        g_Bzr_bot[r] = (c < 128) ? Wlz[(128 + k) * 128 + c]
                                 : Wlr[(128 + k) * 128 + (c - 128)];
    }
}

__global__ void k_init(const float* __restrict__ xL) {
    int i = blockIdx.x * blockDim.x + threadIdx.x;
    if (i < NN * HH) g_h[i] = 0.f;
    if (i < TT * NN) { g_dinv_all[i] = 0.f; g_cnt[i] = 0; }
    if (i < NN * FF) g_xmod[i] = xL[i];
}

// ---------------- CSR build (all 12 graphs) ----------------
__global__ void k_deg_all(const int* __restrict__ ei, const float* __restrict__ ea) {
    int e = blockIdx.x * blockDim.x + threadIdx.x;
    if (e >= TT * EE) return;
    int t = e / EE, le = e - t * EE;
    int dst = ei[(size_t)t * 2 * EE + EE + le];
    atomicAdd(&g_dinv_all[t * NN + dst], ea[(size_t)t * EE + le]);
    atomicAdd(&g_cnt[t * NN + dst], 1);
}

__global__ void k_dinv_fin() {
    int i = blockIdx.x * blockDim.x + threadIdx.x;
    if (i < TT * NN) g_dinv_all[i] = rsqrtf(g_dinv_all[i] + 1.0f);  // +1 self loop
}

__global__ __launch_bounds__(1024) void k_scan() {
    int t = blockIdx.x;
    __shared__ int sm[1024];
    __shared__ int s_run;
    if (threadIdx.x == 0) s_run = 0;
    __syncthreads();
    for (int base = 0; base < NN; base += 1024) {
        int idx = base + threadIdx.x;
        int v = (idx < NN) ? g_cnt[t * NN + idx] : 0;
        sm[threadIdx.x] = v;
        __syncthreads();
        for (int off = 1; off < 1024; off <<= 1) {
            int add = (threadIdx.x >= off) ? sm[threadIdx.x - off] : 0;
            __syncthreads();
            sm[threadIdx.x] += add;
            __syncthreads();
        }
        int incl = sm[threadIdx.x];
        int excl = incl - v;
        if (idx < NN) {
            int rs = s_run + excl;
            g_rowstart[t * (NN + 1) + idx] = rs;
            g_cursor[t * NN + idx] = rs;
        }
        __syncthreads();
        if (threadIdx.x == 1023) s_run += incl;
        __syncthreads();
    }
    if (threadIdx.x == 0) g_rowstart[t * (NN + 1) + NN] = s_run;
}

__global__ void k_fill(const int* __restrict__ ei, const float* __restrict__ ea) {
    int e = blockIdx.x * blockDim.x + threadIdx.x;
    if (e >= TT * EE) return;
    int t = e / EE, le = e - t * EE;
    const int* eit = ei + (size_t)t * 2 * EE;
    int s = eit[le], d = eit[EE + le];
    float w = ea[(size_t)t * EE + le];
    float nrm = g_dinv_all[t * NN + s] * w * g_dinv_all[t * NN + d];
    int pos = atomicAdd(&g_cursor[t * NN + d], 1);
    g_csr[(size_t)t * EE + pos] = make_int2(s, __float_as_int(nrm));
}

// ---------------- gathers ----------------
__global__ void k_gather_all(const float* __restrict__ x_seq) {
    int gw = blockIdx.x * (blockDim.x >> 5) + (threadIdx.x >> 5);
    if (gw >= TT * NN) return;
    int t = gw / NN, n = gw - t * NN;
    int lane = threadIdx.x & 31, half = lane >> 4, f = lane & 15;
    const float* x = x_seq + (size_t)t * NN * FF;
    const int2* csr = g_csr + (size_t)t * EE;
    int row = g_rowstart[t * (NN + 1) + n];
    int end = g_rowstart[t * (NN + 1) + n + 1];
    float acc = 0.f;
    if (!half) {
        float di = g_dinv_all[t * NN + n];
        acc = di * di * x[(size_t)n * FF + f];
    }
    for (int e = row + half; e < end; e += 2) {
        int2 ent = csr[e];
        acc += __int_as_float(ent.y) * x[(size_t)ent.x * FF + f];
    }
    acc += __shfl_down_sync(0xFFFFFFFFu, acc, 16);
    if (!half) g_agg_all[(size_t)t * NN * FF + (size_t)n * FF + f] = acc;
}

__global__ void k_gather_one(const float* __restrict__ x, int t,
                             float* __restrict__ outagg) {
    int gw = blockIdx.x * (blockDim.x >> 5) + (threadIdx.x >> 5);
    if (gw >= NN) return;
    int n = gw;
    int lane = threadIdx.x & 31, half = lane >> 4, f = lane & 15;
    const int2* csr = g_csr + (size_t)t * EE;
    int row = g_rowstart[t * (NN + 1) + n];
    int end = g_rowstart[t * (NN + 1) + n + 1];
    float acc = 0.f;
    if (!half) {
        float di = g_dinv_all[t * NN + n];
        acc = di * di * x[(size_t)n * FF + f];
    }
    for (int e = row + half; e < end; e += 2) {
        int2 ent = csr[e];
        acc += __int_as_float(ent.y) * x[(size_t)ent.x * FF + f];
    }
    acc += __shfl_down_sync(0xFFFFFFFFu, acc, 16);
    if (!half) outagg[(size_t)n * FF + f] = acc;
}

// ---------------- fused gate GEMMs ----------------
__device__ __forceinline__ float sigmoidf_(float v) {
    return 1.0f / (1.0f + __expf(-v));
}

// merged z|r: 128 rows x 256 cols per block, 256 threads, 8x16 per thread
__global__ __launch_bounds__(256) void k_gate_zr(const float* __restrict__ agg,
                                                 int t, int mode) {
    __shared__ __align__(16) float As[16 * 128];
    __shared__ __align__(16) float Bs[16 * 256];
    int tid = threadIdx.x;
    int n0 = blockIdx.x * 128;
    const float* hsrc = mode ? g_hw : g_h;
    const unsigned char* me = g_meff + (size_t)t * NN;

    unsigned long long accp[8][8];
#pragma unroll
    for (int i = 0; i < 8; ++i)
#pragma unroll
        for (int j = 0; j < 8; ++j) accp[i][j] = 0ull;

    int ty = tid >> 4, tx = tid & 15;
    int lr = tid >> 1, lq = tid & 1;
    int bk = tid >> 4, bc = (tid & 15) * 16;

    int nA = n0 + lr;
    bool rowValid = (nA < NN);
    bool rowOn = rowValid;
    if (rowValid && mode == 0) rowOn = (me[nA] != 0);

    for (int chunk = 0; chunk < 9; ++chunk) {
        if (chunk == 0) {
#pragma unroll
            for (int h2 = 0; h2 < 2; ++h2) {
                int kq = lq + 2 * h2;
                float4 v = make_float4(0.f, 0.f, 0.f, 0.f);
                if (rowValid) v = *(const float4*)(agg + (size_t)nA * 16 + 4 * kq);
                As[(4 * kq + 0) * 128 + lr] = v.x;
                As[(4 * kq + 1) * 128 + lr] = v.y;
                As[(4 * kq + 2) * 128 + lr] = v.z;
                As[(4 * kq + 3) * 128 + lr] = v.w;
            }
        } else {
            int kb = (chunk - 1) * 16;
#pragma unroll
            for (int h2 = 0; h2 < 2; ++h2) {
                int kq = lq + 2 * h2;
                float4 v = make_float4(0.f, 0.f, 0.f, 0.f);
                if (rowOn) v = *(const float4*)(hsrc + (size_t)nA * HH + kb + 4 * kq);
                As[(4 * kq + 0) * 128 + lr] = v.x;
                As[(4 * kq + 1) * 128 + lr] = v.y;
                As[(4 * kq + 2) * 128 + lr] = v.z;
                As[(4 * kq + 3) * 128 + lr] = v.w;
            }
        }
        {
            const float* Bg = (chunk == 0)
                ? (g_Bzr_top + bk * 256 + bc)
                : (g_Bzr_bot + ((chunk - 1) * 16 + bk) * 256 + bc);
            *(float4*)&Bs[bk * 256 + bc]      = *(const float4*)Bg;
            *(float4*)&Bs[bk * 256 + bc + 4]  = *(const float4*)(Bg + 4);
            *(float4*)&Bs[bk * 256 + bc + 8]  = *(const float4*)(Bg + 8);
            *(float4*)&Bs[bk * 256 + bc + 12] = *(const float4*)(Bg + 12);
        }
        __syncthreads();
#pragma unroll
        for (int kk = 0; kk < 16; ++kk) {
            float ra[8];
            *(float4*)ra       = *(float4*)&As[kk * 128 + ty * 8];
            *(float4*)(ra + 4) = *(float4*)&As[kk * 128 + ty * 8 + 4];
            ulonglong2 b01 = *(ulonglong2*)&Bs[kk * 256 + tx * 16];
            ulonglong2 b23 = *(ulonglong2*)&Bs[kk * 256 + tx * 16 + 4];
            ulonglong2 b45 = *(ulonglong2*)&Bs[kk * 256 + tx * 16 + 8];
            ulonglong2 b67 = *(ulonglong2*)&Bs[kk * 256 + tx * 16 + 12];
            unsigned long long rbp[8] = {b01.x, b01.y, b23.x, b23.y,
                                         b45.x, b45.y, b67.x, b67.y};
#pragma unroll
            for (int i = 0; i < 8; ++i) {
                unsigned long long rap = pack2(ra[i], ra[i]);
#pragma unroll
                for (int j = 0; j < 8; ++j) fma2(accp[i][j], rap, rbp[j]);
            }
        }
        __syncthreads();
    }

    bool isR = (tx >= 8);
    int cbase = (tx & 7) * 16;
#pragma unroll
    for (int i = 0; i < 8; ++i) {
        int n = n0 + ty * 8 + i;
        if (n >= NN) continue;
        bool on = true;
        if (isR && mode == 0) on = (me[n] != 0);
#pragma unroll
        for (int jp = 0; jp < 8; ++jp) {
            float2 v = unpack2(accp[i][jp]);
            int c = cbase + 2 * jp;
            int cg = (isR ? 128 : 0) + c;
            float s0 = sigmoidf_(v.x + g_bzr[cg]);
            float s1 = sigmoidf_(v.y + g_bzr[cg + 1]);
            if (!isR) {
                g_z[(size_t)n * HH + c]     = s0;
                g_z[(size_t)n * HH + c + 1] = s1;
            } else {
                float h0 = on ? hsrc[(size_t)n * HH + c]     : 0.f;
                float h1 = on ? hsrc[(size_t)n * HH + c + 1] : 0.f;
                g_hr[(size_t)n * HH + c]     = h0 * s0;
                g_hr[(size_t)n * HH + c + 1] = h1 * s1;
            }
        }
    }
}

// h~: 128x128 per block
__global__ __launch_bounds__(256) void k_gate_h(const float* __restrict__ agg,
                                                int t, int mode,
                                                const float* __restrict__ Wlh_bot) {
    __shared__ __align__(16) float As[16 * 128];
    __shared__ __align__(16) float Bs[16 * 128];
    int tid = threadIdx.x;
    int n0 = blockIdx.x * 128;
    const float* hsrc = mode ? g_hw : g_h;
    const unsigned char* me = g_meff + (size_t)t * NN;
    const unsigned char* mk = g_maskc + (size_t)t * NN;

    unsigned long long accp[8][4];
#pragma unroll
    for (int i = 0; i < 8; ++i)
#pragma unroll
        for (int j = 0; j < 4; ++j) accp[i][j] = 0ull;

    int ty = tid >> 4, tx = tid & 15;
    int lr = tid >> 1, lq = tid & 1;
    int bk = tid >> 4, bc = (tid & 15) * 8;

    int nA = n0 + lr;
    bool rowValid = (nA < NN);

    for (int chunk = 0; chunk < 9; ++chunk) {
        if (chunk == 0) {
#pragma unroll
            for (int h2 = 0; h2 < 2; ++h2) {
                int kq = lq + 2 * h2;
                float4 v = make_float4(0.f, 0.f, 0.f, 0.f);
                if (rowValid) v = *(const float4*)(agg + (size_t)nA * 16 + 4 * kq);
                As[(4 * kq + 0) * 128 + lr] = v.x;
                As[(4 * kq + 1) * 128 + lr] = v.y;
                As[(4 * kq + 2) * 128 + lr] = v.z;
                As[(4 * kq + 3) * 128 + lr] = v.w;
            }
        } else {
            int kb = (chunk - 1) * 16;
#pragma unroll
            for (int h2 = 0; h2 < 2; ++h2) {
                int kq = lq + 2 * h2;
                float4 v = make_float4(0.f, 0.f, 0.f, 0.f);
                if (rowValid) v = *(const float4*)(g_hr + (size_t)nA * HH + kb + 4 * kq);
                As[(4 * kq + 0) * 128 + lr] = v.x;
                As[(4 * kq + 1) * 128 + lr] = v.y;
                As[(4 * kq + 2) * 128 + lr] = v.z;
                As[(4 * kq + 3) * 128 + lr] = v.w;
            }
        }
        {
            const float* Bg = (chunk == 0)
                ? (g_Bh_top + bk * 128 + bc)
                : (Wlh_bot + ((size_t)((chunk - 1) * 16 + bk)) * 128 + bc);
            *(float4*)&Bs[bk * 128 + bc]     = *(const float4*)Bg;
            *(float4*)&Bs[bk * 128 + bc + 4] = *(const float4*)(Bg + 4);
        }
        __syncthreads();
#pragma unroll
        for (int kk = 0; kk < 16; ++kk) {
            float ra[8];
            *(float4*)ra       = *(float4*)&As[kk * 128 + ty * 8];
            *(float4*)(ra + 4) = *(float4*)&As[kk * 128 + ty * 8 + 4];
            ulonglong2 b01 = *(ulonglong2*)&Bs[kk * 128 + tx * 8];
            ulonglong2 b23 = *(ulonglong2*)&Bs[kk * 128 + tx * 8 + 4];
            unsigned long long rbp[4] = {b01.x, b01.y, b23.x, b23.y};
#pragma unroll
            for (int i = 0; i < 8; ++i) {
                unsigned long long rap = pack2(ra[i], ra[i]);
                fma2(accp[i][0], rap, rbp[0]);
                fma2(accp[i][1], rap, rbp[1]);
                fma2(accp[i][2], rap, rbp[2]);
                fma2(accp[i][3], rap, rbp[3]);
            }
        }
        __syncthreads();
    }

#pragma unroll
    for (int i = 0; i < 8; ++i) {
        int n = n0 + ty * 8 + i;
        if (n >= NN) continue;
        bool on = mode ? true : (me[n] != 0);
        bool wr = mode ? true : (mk[n] != 0);
#pragma unroll
        for (int jp = 0; jp < 4; ++jp) {
            float2 v = unpack2(accp[i][jp]);
            int c = tx * 8 + 2 * jp;
#pragma unroll
            for (int u = 0; u < 2; ++u) {
                float val = (u == 0) ? v.x : v.y;
                int cc = c + u;
                float ht = tanhf(val + g_bh[cc]);
                float zv = g_z[(size_t)n * HH + cc];
                float heff = on ? hsrc[(size_t)n * HH + cc] : 0.f;
                float hn = zv * heff + (1.f - zv) * ht;
                if (mode) g_hw[(size_t)n * HH + cc] = hn;
                else if (wr) g_h[(size_t)n * HH + cc] = hn;
            }
        }
    }
}

// ---------------- transition / horizon helpers ----------------
__global__ void k_transition() {
    int i = blockIdx.x * blockDim.x + threadIdx.x;
    if (i >= NN * HH) return;
    int n = i >> 7;
    g_hw[i] = g_maskc[11 * NN + n] ? g_h[i] : 0.f;
}

__global__ void k_pred(float* __restrict__ outk, const float* __restrict__ W,
                       const float* __restrict__ b) {
    int gt = blockIdx.x * blockDim.x + threadIdx.x;
    int warp = gt >> 5, lane = gt & 31;
    if (warp >= NN) return;
    const float* h = g_hw + (size_t)warp * HH;
    float p0 = 0.f, p1 = 0.f, p2 = 0.f;
#pragma unroll
    for (int i = 0; i < 4; ++i) {
        int c = lane + 32 * i;
        float hv = h[c];
        const float* w = W + c * 3;
        p0 += hv * w[0]; p1 += hv * w[1]; p2 += hv * w[2];
    }
#pragma unroll
    for (int o = 16; o > 0; o >>= 1) {
        p0 += __shfl_xor_sync(0xFFFFFFFFu, p0, o);
        p1 += __shfl_xor_sync(0xFFFFFFFFu, p1, o);
        p2 += __shfl_xor_sync(0xFFFFFFFFu, p2, o);
    }
    if (lane == 0) {
        float o0 = p0 + b[0], o1 = p1 + b[1], o2 = p2 + b[2];
        outk[warp * 3 + 0] = o0;
        outk[warp * 3 + 1] = o1;
        outk[warp * 3 + 2] = o2;
        g_xmod[warp * 16 + 0] = o0;   // feeds next horizon step's gather
        g_xmod[warp * 16 + 1] = o1;
        g_xmod[warp * 16 + 2] = o2;
    }
}

// ---------------- launch ----------------
extern "C" void kernel_launch(void* const* d_in, const int* in_sizes, int n_in,
                              void* d_out, int out_size) {
    const float* x_seq = (const float*)d_in[0];
    const int*   ei    = (const int*)d_in[1];
    const float* ea    = (const float*)d_in[2];
    const unsigned char* mraw = (const unsigned char*)d_in[3];
    const float* Wcz = (const float*)d_in[4];
    const float* bcz = (const float*)d_in[5];
    const float* Wlz = (const float*)d_in[6];
    const float* blz = (const float*)d_in[7];
    const float* Wcr = (const float*)d_in[8];
    const float* bcr = (const float*)d_in[9];
    const float* Wlr = (const float*)d_in[10];
    const float* blr = (const float*)d_in[11];
    const float* Wch = (const float*)d_in[12];
    const float* bch = (const float*)d_in[13];
    const float* Wlh = (const float*)d_in[14];
    const float* blh = (const float*)d_in[15];
    const float* hW  = (const float*)d_in[16];
    const float* hb  = (const float*)d_in[17];
    float* out = (float*)d_out;

    void* p;
    cudaGetSymbolAddress(&p, g_agg_all);
    const float* agg_all = (const float*)p;
    cudaGetSymbolAddress(&p, g_aggh);
    float* aggh = (float*)p;
    cudaGetSymbolAddress(&p, g_xmod);
    const float* xmod = (const float*)p;

    const int THR = 256;
    const float* xL = x_seq + (size_t)11 * NN * FF;

    k_detect<<<1, THR>>>(mraw);
    k_convert<<<(NN + THR - 1) / THR, THR>>>(mraw);
    k_fuse<<<(6528 + 128 * 256 + THR - 1) / THR, THR>>>(Wcz, Wlz, blz, bcz,
                                                        Wcr, Wlr, blr, bcr,
                                                        Wch, Wlh, blh, bch);
    k_init<<<(NN * HH + THR - 1) / THR, THR>>>(xL);
    k_deg_all<<<(TT * EE + THR - 1) / THR, THR>>>(ei, ea);
    k_dinv_fin<<<(TT * NN + THR - 1) / THR, THR>>>();
    k_scan<<<TT, 1024>>>();
    k_fill<<<(TT * EE + THR - 1) / THR, THR>>>(ei, ea);
    k_gather_all<<<(TT * NN + 7) / 8, THR>>>(x_seq);

    dim3 gG((NN + 127) / 128);
    const float* Wlh_bot = Wlh + 128 * 128;

    for (int t = 0; t < TT; ++t) {
        const float* aggt = agg_all + (size_t)t * NN * FF;
        k_gate_zr<<<gG, THR>>>(aggt, t, 0);
        k_gate_h<<<gG, THR>>>(aggt, t, 0, Wlh_bot);
    }

    k_transition<<<(NN * HH + THR - 1) / THR, THR>>>();

    const float* agg11 = agg_all + (size_t)11 * NN * FF;

    for (int k = 0; k < HOR; ++k) {
        const float* aggk = agg11;
        if (k > 0) {
            k_gather_one<<<(NN + 7) / 8, THR>>>(xmod, 11, aggh);
            aggk = aggh;
        }
        k_gate_zr<<<gG, THR>>>(aggk, 11, 1);
        k_gate_h<<<gG, THR>>>(aggk, 11, 1, Wlh_bot);
        k_pred<<<(NN * 32 + THR - 1) / THR, THR>>>(out + (size_t)k * NN * OUTD, hW, hb);
    }
}

// round 4
// speedup vs baseline: 1.3254x; 1.3254x over previous
#include <cuda_runtime.h>
#include <math.h>

#define NN 50000
#define EE 1600000
#define TT 12
#define FF 16
#define HH 128
#define OUTD 3
#define HOR 6

// ---------------- scratch (static device globals; no allocation) ----------------
__device__ float g_dinv_all[TT * NN];
__device__ float g_agg_all[(size_t)TT * NN * FF];
__device__ float g_aggh[NN * FF];           // horizon agg (cols 3..15 frozen)
__device__ float g_nrm11[EE];               // precomputed edge norms, graph 11
__device__ float g_z[NN * HH];
__device__ float g_hr[NN * HH];
__device__ float g_h[NN * HH];
__device__ float g_hw[NN * HH];
__device__ unsigned char g_maskc[TT * NN];
__device__ unsigned char g_meff[TT * NN];   // mask[t] & (mask[0]|...|mask[t-1])
__device__ float g_Bzr_top[16 * 256];
__device__ float g_bzr[256];
__device__ float g_Bzr_bot[128 * 256];
__device__ float g_Bh_top[16 * 128];
__device__ float g_bh[128];
__device__ int g_isbyte;

// ---------------- f32x2 packed-FMA helpers ----------------
__device__ __forceinline__ unsigned long long pack2(float lo, float hi) {
    unsigned long long r;
    asm("mov.b64 %0, {%1, %2};" : "=l"(r) : "f"(lo), "f"(hi));
    return r;
}
__device__ __forceinline__ void fma2(unsigned long long& acc,
                                     unsigned long long a, unsigned long long b) {
    asm("fma.rn.f32x2 %0, %1, %2, %0;" : "+l"(acc) : "l"(a), "l"(b));
}
__device__ __forceinline__ float2 unpack2(unsigned long long v) {
    float2 f;
    asm("mov.b64 {%0, %1}, %2;" : "=f"(f.x), "=f"(f.y) : "l"(v));
    return f;
}

// ---------------- mask dtype detection + canonicalization ----------------
__global__ void k_detect(const unsigned char* raw) {
    __shared__ int cnt;
    if (threadIdx.x == 0) cnt = 0;
    __syncthreads();
    int c = 0;
    for (int i = threadIdx.x; i < 4096; i += blockDim.x)
        c += (raw[i] != 0);
    atomicAdd(&cnt, c);
    __syncthreads();
    if (threadIdx.x == 0) g_isbyte = (cnt > 2048) ? 1 : 0;
}

__global__ void k_convert(const unsigned char* raw) {
    int n = blockIdx.x * blockDim.x + threadIdx.x;
    if (n >= NN) return;
    int isb = g_isbyte;
    int seen = 0;
#pragma unroll
    for (int t = 0; t < TT; ++t) {
        int m = isb ? (raw[t * NN + n] != 0)
                    : (((const int*)raw)[t * NN + n] != 0);
        g_maskc[t * NN + n] = (unsigned char)m;
        g_meff[t * NN + n] = (unsigned char)(m & seen);
        seen |= m;
    }
}

// ---------------- weight fusion ----------------
__global__ void k_fuse(const float* __restrict__ Wcz, const float* __restrict__ Wlz,
                       const float* __restrict__ blz, const float* __restrict__ bcz,
                       const float* __restrict__ Wcr, const float* __restrict__ Wlr,
                       const float* __restrict__ blr, const float* __restrict__ bcr,
                       const float* __restrict__ Wch, const float* __restrict__ Wlh,
                       const float* __restrict__ blh, const float* __restrict__ bch) {
    int i = blockIdx.x * blockDim.x + threadIdx.x;
    if (i < 16 * 256) {                           // Bzr_top
        int k = i / 256, c = i % 256, cc = c & 127;
        const float* A = (c < 128) ? Wcz : Wcr;
        const float* B = (c < 128) ? Wlz : Wlr;
        float s = 0.f;
        for (int j = 0; j < 128; ++j) s += A[k * 128 + j] * B[j * 128 + cc];
        g_Bzr_top[i] = s;
    } else if (i < 4096 + 2048) {                 // Bh_top
        int r = i - 4096; int k = r / 128, c = r % 128;
        float s = 0.f;
        for (int j = 0; j < 128; ++j) s += Wch[k * 128 + j] * Wlh[j * 128 + c];
        g_Bh_top[r] = s;
    } else if (i < 6144 + 256) {                  // fused z|r bias
        int c = i - 6144; int cc = c & 127;
        const float* bc = (c < 128) ? bcz : bcr;
        const float* B  = (c < 128) ? Wlz : Wlr;
        const float* bl = (c < 128) ? blz : blr;
        float s = bl[cc];
        for (int j = 0; j < 128; ++j) s += bc[j] * B[j * 128 + cc];
        g_bzr[c] = s;
    } else if (i < 6400 + 128) {                  // fused h bias
        int c = i - 6400;
        float s = blh[c];
        for (int j = 0; j < 128; ++j) s += bch[j] * Wlh[j * 128 + c];
        g_bh[c] = s;
    } else if (i < 6528 + 128 * 256) {            // Bzr_bot pack
        int r = i - 6528; int k = r / 256, c = r % 256;
        g_Bzr_bot[r] = (c < 128) ? Wlz[(128 + k) * 128 + c]
                                 : Wlr[(128 + k) * 128 + (c - 128)];
    }
}

__global__ void k_init() {
    int i = blockIdx.x * blockDim.x + threadIdx.x;
    if (i < NN * HH) g_h[i] = 0.f;
    if (i < TT * NN) g_dinv_all[i] = 0.f;
}

// ---------------- degree / dinv (all 12 graphs, batched) ----------------
__global__ void k_deg_all(const int* __restrict__ ei, const float* __restrict__ ea) {
    int e = blockIdx.x * blockDim.x + threadIdx.x;
    if (e >= TT * EE) return;
    int t = e / EE, le = e - t * EE;
    int dst = ei[(size_t)t * 2 * EE + EE + le];
    atomicAdd(&g_dinv_all[t * NN + dst], ea[(size_t)t * EE + le]);
}

__global__ void k_dinv_fin() {
    int i = blockIdx.x * blockDim.x + threadIdx.x;
    if (i < TT * NN) g_dinv_all[i] = rsqrtf(g_dinv_all[i] + 1.0f);  // +1 self loop
}

// self-loop terms for ALL 12 graphs: agg_all[t][n] = dinv^2 * x[t][n]
__global__ void k_aggself_all(const float* __restrict__ x_seq) {
    int i = blockIdx.x * blockDim.x + threadIdx.x;
    if (i >= TT * NN) return;
    int t = i / NN, n = i - t * NN;
    float di = g_dinv_all[i];
    float s = di * di;
    const float4* xp = (const float4*)(x_seq + (size_t)t * NN * FF + (size_t)n * FF);
    float4* op = (float4*)(g_agg_all + (size_t)t * NN * FF + (size_t)n * FF);
    float4 a = xp[0], b = xp[1], c = xp[2], d = xp[3];
    op[0] = make_float4(s * a.x, s * a.y, s * a.z, s * a.w);
    op[1] = make_float4(s * b.x, s * b.y, s * b.z, s * b.w);
    op[2] = make_float4(s * c.x, s * c.y, s * c.z, s * c.w);
    op[3] = make_float4(s * d.x, s * d.y, s * d.z, s * d.w);
}

#define REDV4(p, a, b, c, d)                                              \
    asm volatile("red.global.add.v4.f32 [%0], {%1,%2,%3,%4};"             \
                 :: "l"(p), "f"(a), "f"(b), "f"(c), "f"(d) : "memory")
#define REDV2(p, a, b)                                                    \
    asm volatile("red.global.add.v2.f32 [%0], {%1,%2};"                   \
                 :: "l"(p), "f"(a), "f"(b) : "memory")
#define RED1(p, a)                                                        \
    asm volatile("red.global.add.f32 [%0], %1;"                           \
                 :: "l"(p), "f"(a) : "memory")

// batched scatter over all 12 graphs; stores nrm for graph 11 as side product
__global__ void k_scatter_all(const int* __restrict__ ei, const float* __restrict__ ea,
                              const float* __restrict__ x_seq) {
    int e = blockIdx.x * blockDim.x + threadIdx.x;
    if (e >= TT * EE) return;
    int t = e / EE, le = e - t * EE;
    const int* eit = ei + (size_t)t * 2 * EE;
    int s = eit[le], d = eit[EE + le];
    const float* dinv = g_dinv_all + t * NN;
    float nrm = dinv[s] * ea[(size_t)t * EE + le] * dinv[d];
    if (t == 11) g_nrm11[le] = nrm;
    const float4* xp = (const float4*)(x_seq + (size_t)t * NN * FF + (size_t)s * FF);
    float4 a = xp[0], b = xp[1], c = xp[2], dd = xp[3];
    float* o = g_agg_all + (size_t)t * NN * FF + (size_t)d * FF;
    REDV4(o + 0,  nrm * a.x,  nrm * a.y,  nrm * a.z,  nrm * a.w);
    REDV4(o + 4,  nrm * b.x,  nrm * b.y,  nrm * b.z,  nrm * b.w);
    REDV4(o + 8,  nrm * c.x,  nrm * c.y,  nrm * c.z,  nrm * c.w);
    REDV4(o + 12, nrm * dd.x, nrm * dd.y, nrm * dd.z, nrm * dd.w);
}

// ---------------- fused gate GEMMs (R2-proven shapes) ----------------
__device__ __forceinline__ float sigmoidf_(float v) {
    return 1.0f / (1.0f + __expf(-v));
}

// z|r = sigmoid([agg | h_eff] @ [Bzr_top;Bzr_bot] + bzr); stores z and hr=h_eff*r
__global__ __launch_bounds__(256) void k_gate_zr(const float* __restrict__ agg,
                                                 int t, int mode) {
    __shared__ __align__(16) float As[16 * 128];
    __shared__ __align__(16) float Bs[16 * 128];
    int tid = threadIdx.x;
    int n0 = blockIdx.x * 128;
    int c0 = blockIdx.y * 128;  // 0 -> z, 128 -> r
    const float* hsrc = mode ? g_hw : g_h;
    const unsigned char* me = g_meff + (size_t)t * NN;

    unsigned long long accp[8][4];
#pragma unroll
    for (int i = 0; i < 8; ++i)
#pragma unroll
        for (int j = 0; j < 4; ++j) accp[i][j] = 0ull;

    int ty = tid >> 4, tx = tid & 15;
    int lr = tid >> 1, lq = tid & 1;
    int bk = tid >> 4, bc = (tid & 15) * 8;

    int nA = n0 + lr;
    bool rowValid = (nA < NN);
    bool rowOn = rowValid;
    if (rowValid && mode == 0) rowOn = (me[nA] != 0);

    for (int chunk = 0; chunk < 9; ++chunk) {
        if (chunk == 0) {
#pragma unroll
            for (int h2 = 0; h2 < 2; ++h2) {
                int kq = lq + 2 * h2;
                float4 v = make_float4(0.f, 0.f, 0.f, 0.f);
                if (rowValid) v = *(const float4*)(agg + (size_t)nA * 16 + 4 * kq);
                As[(4 * kq + 0) * 128 + lr] = v.x;
                As[(4 * kq + 1) * 128 + lr] = v.y;
                As[(4 * kq + 2) * 128 + lr] = v.z;
                As[(4 * kq + 3) * 128 + lr] = v.w;
            }
        } else {
            int kb = (chunk - 1) * 16;
#pragma unroll
            for (int h2 = 0; h2 < 2; ++h2) {
                int kq = lq + 2 * h2;
                float4 v = make_float4(0.f, 0.f, 0.f, 0.f);
                if (rowOn) v = *(const float4*)(hsrc + (size_t)nA * HH + kb + 4 * kq);
                As[(4 * kq + 0) * 128 + lr] = v.x;
                As[(4 * kq + 1) * 128 + lr] = v.y;
                As[(4 * kq + 2) * 128 + lr] = v.z;
                As[(4 * kq + 3) * 128 + lr] = v.w;
            }
        }
        {
            const float* Bg = (chunk == 0)
                ? (g_Bzr_top + bk * 256 + c0 + bc)
                : (g_Bzr_bot + ((chunk - 1) * 16 + bk) * 256 + c0 + bc);
            *(float4*)&Bs[bk * 128 + bc]     = *(const float4*)Bg;
            *(float4*)&Bs[bk * 128 + bc + 4] = *(const float4*)(Bg + 4);
        }
        __syncthreads();
#pragma unroll
        for (int kk = 0; kk < 16; ++kk) {
            float ra[8];
            *(float4*)ra       = *(float4*)&As[kk * 128 + ty * 8];
            *(float4*)(ra + 4) = *(float4*)&As[kk * 128 + ty * 8 + 4];
            ulonglong2 b01 = *(ulonglong2*)&Bs[kk * 128 + tx * 8];
            ulonglong2 b23 = *(ulonglong2*)&Bs[kk * 128 + tx * 8 + 4];
            unsigned long long rbp[4] = {b01.x, b01.y, b23.x, b23.y};
#pragma unroll
            for (int i = 0; i < 8; ++i) {
                unsigned long long rap = pack2(ra[i], ra[i]);
                fma2(accp[i][0], rap, rbp[0]);
                fma2(accp[i][1], rap, rbp[1]);
                fma2(accp[i][2], rap, rbp[2]);
                fma2(accp[i][3], rap, rbp[3]);
            }
        }
        __syncthreads();
    }

    bool isR = (c0 != 0);
#pragma unroll
    for (int i = 0; i < 8; ++i) {
        int n = n0 + ty * 8 + i;
        if (n >= NN) continue;
        bool on = true;
        if (isR && mode == 0) on = (me[n] != 0);
#pragma unroll
        for (int jp = 0; jp < 4; ++jp) {
            float2 v = unpack2(accp[i][jp]);
            int c = tx * 8 + 2 * jp;
            float s0 = sigmoidf_(v.x + g_bzr[c0 + c]);
            float s1 = sigmoidf_(v.y + g_bzr[c0 + c + 1]);
            if (!isR) {
                g_z[(size_t)n * HH + c]     = s0;
                g_z[(size_t)n * HH + c + 1] = s1;
            } else {
                float h0 = on ? hsrc[(size_t)n * HH + c]     : 0.f;
                float h1 = on ? hsrc[(size_t)n * HH + c + 1] : 0.f;
                g_hr[(size_t)n * HH + c]     = h0 * s0;
                g_hr[(size_t)n * HH + c + 1] = h1 * s1;
            }
        }
    }
}

__global__ __launch_bounds__(256) void k_gate_h(const float* __restrict__ agg,
                                                int t, int mode,
                                                const float* __restrict__ Wlh_bot) {
    __shared__ __align__(16) float As[16 * 128];
    __shared__ __align__(16) float Bs[16 * 128];
    int tid = threadIdx.x;
    int n0 = blockIdx.x * 128;
    const float* hsrc = mode ? g_hw : g_h;
    const unsigned char* me = g_meff + (size_t)t * NN;
    const unsigned char* mk = g_maskc + (size_t)t * NN;

    unsigned long long accp[8][4];
#pragma unroll
    for (int i = 0; i < 8; ++i)
#pragma unroll
        for (int j = 0; j < 4; ++j) accp[i][j] = 0ull;

    int ty = tid >> 4, tx = tid & 15;
    int lr = tid >> 1, lq = tid & 1;
    int bk = tid >> 4, bc = (tid & 15) * 8;

    int nA = n0 + lr;
    bool rowValid = (nA < NN);

    for (int chunk = 0; chunk < 9; ++chunk) {
        if (chunk == 0) {
#pragma unroll
            for (int h2 = 0; h2 < 2; ++h2) {
                int kq = lq + 2 * h2;
                float4 v = make_float4(0.f, 0.f, 0.f, 0.f);
                if (rowValid) v = *(const float4*)(agg + (size_t)nA * 16 + 4 * kq);
                As[(4 * kq + 0) * 128 + lr] = v.x;
                As[(4 * kq + 1) * 128 + lr] = v.y;
                As[(4 * kq + 2) * 128 + lr] = v.z;
                As[(4 * kq + 3) * 128 + lr] = v.w;
            }
        } else {
            int kb = (chunk - 1) * 16;
#pragma unroll
            for (int h2 = 0; h2 < 2; ++h2) {
                int kq = lq + 2 * h2;
                float4 v = make_float4(0.f, 0.f, 0.f, 0.f);
                if (rowValid) v = *(const float4*)(g_hr + (size_t)nA * HH + kb + 4 * kq);
                As[(4 * kq + 0) * 128 + lr] = v.x;
                As[(4 * kq + 1) * 128 + lr] = v.y;
                As[(4 * kq + 2) * 128 + lr] = v.z;
                As[(4 * kq + 3) * 128 + lr] = v.w;
            }
        }
        {
            const float* Bg = (chunk == 0)
                ? (g_Bh_top + bk * 128 + bc)
                : (Wlh_bot + ((size_t)((chunk - 1) * 16 + bk)) * 128 + bc);
            *(float4*)&Bs[bk * 128 + bc]     = *(const float4*)Bg;
            *(float4*)&Bs[bk * 128 + bc + 4] = *(const float4*)(Bg + 4);
        }
        __syncthreads();
#pragma unroll
        for (int kk = 0; kk < 16; ++kk) {
            float ra[8];
            *(float4*)ra       = *(float4*)&As[kk * 128 + ty * 8];
            *(float4*)(ra + 4) = *(float4*)&As[kk * 128 + ty * 8 + 4];
            ulonglong2 b01 = *(ulonglong2*)&Bs[kk * 128 + tx * 8];
            ulonglong2 b23 = *(ulonglong2*)&Bs[kk * 128 + tx * 8 + 4];
            unsigned long long rbp[4] = {b01.x, b01.y, b23.x, b23.y};
#pragma unroll
            for (int i = 0; i < 8; ++i) {
                unsigned long long rap = pack2(ra[i], ra[i]);
                fma2(accp[i][0], rap, rbp[0]);
                fma2(accp[i][1], rap, rbp[1]);
                fma2(accp[i][2], rap, rbp[2]);
                fma2(accp[i][3], rap, rbp[3]);
            }
        }
        __syncthreads();
    }

#pragma unroll
    for (int i = 0; i < 8; ++i) {
        int n = n0 + ty * 8 + i;
        if (n >= NN) continue;
        bool on = mode ? true : (me[n] != 0);
        bool wr = mode ? true : (mk[n] != 0);
#pragma unroll
        for (int jp = 0; jp < 4; ++jp) {
            float2 v = unpack2(accp[i][jp]);
            int c = tx * 8 + 2 * jp;
#pragma unroll
            for (int u = 0; u < 2; ++u) {
                float val = (u == 0) ? v.x : v.y;
                int cc = c + u;
                float ht = tanhf(val + g_bh[cc]);
                float zv = g_z[(size_t)n * HH + cc];
                float heff = on ? hsrc[(size_t)n * HH + cc] : 0.f;
                float hn = zv * heff + (1.f - zv) * ht;
                if (mode) g_hw[(size_t)n * HH + cc] = hn;
                else if (wr) g_h[(size_t)n * HH + cc] = hn;
            }
        }
    }
}

// ---------------- transition / horizon helpers ----------------
__global__ void k_transition(const float* __restrict__ agg11) {
    int i = blockIdx.x * blockDim.x + threadIdx.x;
    if (i < NN * HH) {
        int n = i >> 7;
        g_hw[i] = g_maskc[11 * NN + n] ? g_h[i] : 0.f;
    }
    if (i < NN * FF) g_aggh[i] = agg11[i];  // freeze cols 3..15 (0..2 rewritten)
}

// per-step horizon: re-init agg cols 0..2 with self-term from prev prediction
__global__ void k_aggh_init3(const float* __restrict__ pred) {
    int i = blockIdx.x * blockDim.x + threadIdx.x;
    if (i >= NN * OUTD) return;
    int n = i / 3, c = i - n * 3;
    float di = g_dinv_all[11 * NN + n];
    g_aggh[n * FF + c] = di * di * pred[i];
}

__global__ void k_scatter3(const int* __restrict__ ei11,
                           const float* __restrict__ pred) {
    int e = blockIdx.x * blockDim.x + threadIdx.x;
    if (e >= EE) return;
    int s = ei11[e], d = ei11[EE + e];
    float nrm = g_nrm11[e];
    float p0 = pred[s * 3 + 0], p1 = pred[s * 3 + 1], p2 = pred[s * 3 + 2];
    float* o = g_aggh + (size_t)d * FF;
    REDV2(o, nrm * p0, nrm * p1);
    RED1(o + 2, nrm * p2);
}

__global__ void k_pred(float* __restrict__ outk, const float* __restrict__ W,
                       const float* __restrict__ b) {
    int gt = blockIdx.x * blockDim.x + threadIdx.x;
    int warp = gt >> 5, lane = gt & 31;
    if (warp >= NN) return;
    const float* h = g_hw + (size_t)warp * HH;
    float p0 = 0.f, p1 = 0.f, p2 = 0.f;
#pragma unroll
    for (int i = 0; i < 4; ++i) {
        int c = lane + 32 * i;
        float hv = h[c];
        const float* w = W + c * 3;
        p0 += hv * w[0]; p1 += hv * w[1]; p2 += hv * w[2];
    }
#pragma unroll
    for (int o = 16; o > 0; o >>= 1) {
        p0 += __shfl_xor_sync(0xFFFFFFFFu, p0, o);
        p1 += __shfl_xor_sync(0xFFFFFFFFu, p1, o);
        p2 += __shfl_xor_sync(0xFFFFFFFFu, p2, o);
    }
    if (lane == 0) {
        outk[warp * 3 + 0] = p0 + b[0];
        outk[warp * 3 + 1] = p1 + b[1];
        outk[warp * 3 + 2] = p2 + b[2];
    }
}

// ---------------- launch ----------------
extern "C" void kernel_launch(void* const* d_in, const int* in_sizes, int n_in,
                              void* d_out, int out_size) {
    const float* x_seq = (const float*)d_in[0];
    const int*   ei    = (const int*)d_in[1];
    const float* ea    = (const float*)d_in[2];
    const unsigned char* mraw = (const unsigned char*)d_in[3];
    const float* Wcz = (const float*)d_in[4];
    const float* bcz = (const float*)d_in[5];
    const float* Wlz = (const float*)d_in[6];
    const float* blz = (const float*)d_in[7];
    const float* Wcr = (const float*)d_in[8];
    const float* bcr = (const float*)d_in[9];
    const float* Wlr = (const float*)d_in[10];
    const float* blr = (const float*)d_in[11];
    const float* Wch = (const float*)d_in[12];
    const float* bch = (const float*)d_in[13];
    const float* Wlh = (const float*)d_in[14];
    const float* blh = (const float*)d_in[15];
    const float* hW  = (const float*)d_in[16];
    const float* hb  = (const float*)d_in[17];
    float* out = (float*)d_out;

    void* p;
    cudaGetSymbolAddress(&p, g_agg_all);
    const float* agg_all = (const float*)p;
    cudaGetSymbolAddress(&p, g_aggh);
    const float* aggh = (const float*)p;

    const int THR = 256;

    k_detect<<<1, THR>>>(mraw);
    k_convert<<<(NN + THR - 1) / THR, THR>>>(mraw);
    k_fuse<<<(6528 + 128 * 256 + THR - 1) / THR, THR>>>(Wcz, Wlz, blz, bcz,
                                                        Wcr, Wlr, blr, bcr,
                                                        Wch, Wlh, blh, bch);
    k_init<<<(NN * HH + THR - 1) / THR, THR>>>();
    k_deg_all<<<(TT * EE + THR - 1) / THR, THR>>>(ei, ea);
    k_dinv_fin<<<(TT * NN + THR - 1) / THR, THR>>>();
    k_aggself_all<<<(TT * NN + THR - 1) / THR, THR>>>(x_seq);
    k_scatter_all<<<(TT * EE + THR - 1) / THR, THR>>>(ei, ea, x_seq);

    dim3 gZR((NN + 127) / 128, 2), gH((NN + 127) / 128, 1);
    const float* Wlh_bot = Wlh + 128 * 128;

    for (int t = 0; t < TT; ++t) {
        const float* aggt = agg_all + (size_t)t * NN * FF;
        k_gate_zr<<<gZR, THR>>>(aggt, t, 0);
        k_gate_h<<<gH, THR>>>(aggt, t, 0, Wlh_bot);
    }

    const float* agg11 = agg_all + (size_t)11 * NN * FF;
    k_transition<<<(NN * HH + THR - 1) / THR, THR>>>(agg11);

    const int* eiL = ei + (size_t)11 * 2 * EE;

    for (int k = 0; k < HOR; ++k) {
        const float* aggk = agg11;
        if (k > 0) {
            const float* predPrev = out + (size_t)(k - 1) * NN * OUTD;
            k_aggh_init3<<<(NN * OUTD + THR - 1) / THR, THR>>>(predPrev);
            k_scatter3<<<(EE + THR - 1) / THR, THR>>>(eiL, predPrev);
            aggk = aggh;
        }
        k_gate_zr<<<gZR, THR>>>(aggk, 11, 1);
        k_gate_h<<<gH, THR>>>(aggk, 11, 1, Wlh_bot);
        k_pred<<<(NN * 32 + THR - 1) / THR, THR>>>(out + (size_t)k * NN * OUTD, hW, hb);
    }
}

// round 5
// speedup vs baseline: 1.4341x; 1.0821x over previous
#include <cuda_runtime.h>
#include <math.h>

#define NN 50000
#define EE 1600000
#define TT 12
#define FF 16
#define HH 128
#define OUTD 3
#define HOR 6
#define HRS 132   // hr smem row stride (pad to reduce write conflicts)

// smem floats: As 144*128 + hrs 128*HRS + zs 128*128 + Bs 2*16*128
#define SMEM_CELL ((144 * 128 + 128 * HRS + 128 * 128 + 2 * 16 * 128) * 4)

// ---------------- scratch (static device globals; no allocation) ----------------
__device__ float g_dinv_all[TT * NN];
__device__ float g_agg_all[(size_t)TT * NN * FF];
__device__ float g_aggh[NN * FF];           // horizon agg (cols 3..15 frozen)
__device__ float g_nrm11[EE];               // precomputed edge norms, graph 11
__device__ float g_h[NN * HH];
__device__ float g_hw[NN * HH];
__device__ unsigned char g_maskc[TT * NN];
__device__ unsigned char g_meff[TT * NN];
__device__ float g_Bzr_top[16 * 256];
__device__ float g_bzr[256];
__device__ float g_Bzr_bot[128 * 256];
__device__ float g_Bh_top[16 * 128];
__device__ float g_bh[128];
__device__ int g_isbyte;

// ---------------- f32x2 packed-FMA helpers ----------------
__device__ __forceinline__ unsigned long long pack2(float lo, float hi) {
    unsigned long long r;
    asm("mov.b64 %0, {%1, %2};" : "=l"(r) : "f"(lo), "f"(hi));
    return r;
}
__device__ __forceinline__ void fma2(unsigned long long& acc,
                                     unsigned long long a, unsigned long long b) {
    asm("fma.rn.f32x2 %0, %1, %2, %0;" : "+l"(acc) : "l"(a), "l"(b));
}
__device__ __forceinline__ float2 unpack2(unsigned long long v) {
    float2 f;
    asm("mov.b64 {%0, %1}, %2;" : "=f"(f.x), "=f"(f.y) : "l"(v));
    return f;
}

// ---------------- mask dtype detection + canonicalization ----------------
__global__ void k_detect(const unsigned char* raw) {
    __shared__ int cnt;
    if (threadIdx.x == 0) cnt = 0;
    __syncthreads();
    int c = 0;
    for (int i = threadIdx.x; i < 4096; i += blockDim.x)
        c += (raw[i] != 0);
    atomicAdd(&cnt, c);
    __syncthreads();
    if (threadIdx.x == 0) g_isbyte = (cnt > 2048) ? 1 : 0;
}

__global__ void k_convert(const unsigned char* raw) {
    int n = blockIdx.x * blockDim.x + threadIdx.x;
    if (n >= NN) return;
    int isb = g_isbyte;
    int seen = 0;
#pragma unroll
    for (int t = 0; t < TT; ++t) {
        int m = isb ? (raw[t * NN + n] != 0)
                    : (((const int*)raw)[t * NN + n] != 0);
        g_maskc[t * NN + n] = (unsigned char)m;
        g_meff[t * NN + n] = (unsigned char)(m & seen);
        seen |= m;
    }
}

// ---------------- weight fusion ----------------
__global__ void k_fuse(const float* __restrict__ Wcz, const float* __restrict__ Wlz,
                       const float* __restrict__ blz, const float* __restrict__ bcz,
                       const float* __restrict__ Wcr, const float* __restrict__ Wlr,
                       const float* __restrict__ blr, const float* __restrict__ bcr,
                       const float* __restrict__ Wch, const float* __restrict__ Wlh,
                       const float* __restrict__ blh, const float* __restrict__ bch) {
    int i = blockIdx.x * blockDim.x + threadIdx.x;
    if (i < 16 * 256) {                           // Bzr_top
        int k = i / 256, c = i % 256, cc = c & 127;
        const float* A = (c < 128) ? Wcz : Wcr;
        const float* B = (c < 128) ? Wlz : Wlr;
        float s = 0.f;
        for (int j = 0; j < 128; ++j) s += A[k * 128 + j] * B[j * 128 + cc];
        g_Bzr_top[i] = s;
    } else if (i < 4096 + 2048) {                 // Bh_top
        int r = i - 4096; int k = r / 128, c = r % 128;
        float s = 0.f;
        for (int j = 0; j < 128; ++j) s += Wch[k * 128 + j] * Wlh[j * 128 + c];
        g_Bh_top[r] = s;
    } else if (i < 6144 + 256) {                  // fused z|r bias
        int c = i - 6144; int cc = c & 127;
        const float* bc = (c < 128) ? bcz : bcr;
        const float* B  = (c < 128) ? Wlz : Wlr;
        const float* bl = (c < 128) ? blz : blr;
        float s = bl[cc];
        for (int j = 0; j < 128; ++j) s += bc[j] * B[j * 128 + cc];
        g_bzr[c] = s;
    } else if (i < 6400 + 128) {                  // fused h bias
        int c = i - 6400;
        float s = blh[c];
        for (int j = 0; j < 128; ++j) s += bch[j] * Wlh[j * 128 + c];
        g_bh[c] = s;
    } else if (i < 6528 + 128 * 256) {            // Bzr_bot pack
        int r = i - 6528; int k = r / 256, c = r % 256;
        g_Bzr_bot[r] = (c < 128) ? Wlz[(128 + k) * 128 + c]
                                 : Wlr[(128 + k) * 128 + (c - 128)];
    }
}

__global__ void k_init() {
    int i = blockIdx.x * blockDim.x + threadIdx.x;
    if (i < NN * HH) g_h[i] = 0.f;
    if (i < TT * NN) g_dinv_all[i] = 0.f;
}

// ---------------- degree / dinv / aggregation (batched) ----------------
__global__ void k_deg_all(const int* __restrict__ ei, const float* __restrict__ ea) {
    int e = blockIdx.x * blockDim.x + threadIdx.x;
    if (e >= TT * EE) return;
    int t = e / EE, le = e - t * EE;
    int dst = ei[(size_t)t * 2 * EE + EE + le];
    atomicAdd(&g_dinv_all[t * NN + dst], ea[(size_t)t * EE + le]);
}

__global__ void k_dinv_fin() {
    int i = blockIdx.x * blockDim.x + threadIdx.x;
    if (i < TT * NN) g_dinv_all[i] = rsqrtf(g_dinv_all[i] + 1.0f);
}

__global__ void k_aggself_all(const float* __restrict__ x_seq) {
    int i = blockIdx.x * blockDim.x + threadIdx.x;
    if (i >= TT * NN) return;
    int t = i / NN, n = i - t * NN;
    float di = g_dinv_all[i];
    float s = di * di;
    const float4* xp = (const float4*)(x_seq + (size_t)t * NN * FF + (size_t)n * FF);
    float4* op = (float4*)(g_agg_all + (size_t)t * NN * FF + (size_t)n * FF);
    float4 a = xp[0], b = xp[1], c = xp[2], d = xp[3];
    op[0] = make_float4(s * a.x, s * a.y, s * a.z, s * a.w);
    op[1] = make_float4(s * b.x, s * b.y, s * b.z, s * b.w);
    op[2] = make_float4(s * c.x, s * c.y, s * c.z, s * c.w);
    op[3] = make_float4(s * d.x, s * d.y, s * d.z, s * d.w);
}

#define REDV4(p, a, b, c, d)                                              \
    asm volatile("red.global.add.v4.f32 [%0], {%1,%2,%3,%4};"             \
                 :: "l"(p), "f"(a), "f"(b), "f"(c), "f"(d) : "memory")
#define REDV2(p, a, b)                                                    \
    asm volatile("red.global.add.v2.f32 [%0], {%1,%2};"                   \
                 :: "l"(p), "f"(a), "f"(b) : "memory")
#define RED1(p, a)                                                        \
    asm volatile("red.global.add.f32 [%0], %1;"                           \
                 :: "l"(p), "f"(a) : "memory")

__global__ void k_scatter_all(const int* __restrict__ ei, const float* __restrict__ ea,
                              const float* __restrict__ x_seq) {
    int e = blockIdx.x * blockDim.x + threadIdx.x;
    if (e >= TT * EE) return;
    int t = e / EE, le = e - t * EE;
    const int* eit = ei + (size_t)t * 2 * EE;
    int s = eit[le], d = eit[EE + le];
    const float* dinv = g_dinv_all + t * NN;
    float nrm = dinv[s] * ea[(size_t)t * EE + le] * dinv[d];
    if (t == 11) g_nrm11[le] = nrm;
    const float4* xp = (const float4*)(x_seq + (size_t)t * NN * FF + (size_t)s * FF);
    float4 a = xp[0], b = xp[1], c = xp[2], dd = xp[3];
    float* o = g_agg_all + (size_t)t * NN * FF + (size_t)d * FF;
    REDV4(o + 0,  nrm * a.x,  nrm * a.y,  nrm * a.z,  nrm * a.w);
    REDV4(o + 4,  nrm * b.x,  nrm * b.y,  nrm * b.z,  nrm * b.w);
    REDV4(o + 8,  nrm * c.x,  nrm * c.y,  nrm * c.z,  nrm * c.w);
    REDV4(o + 12, nrm * dd.x, nrm * dd.y, nrm * dd.z, nrm * dd.w);
}

// ---------------- fused TGCN cell: z, r, h~ and state update in ONE kernel ----------------
__device__ __forceinline__ float sigmoidf_(float v) {
    return 1.0f / (1.0f + __expf(-v));
}

__device__ __forceinline__ void ldB_zr(float* dst, int chunk, int c0, int bk, int bc) {
    const float* Bg = (chunk == 0)
        ? (g_Bzr_top + bk * 256 + c0 + bc)
        : (g_Bzr_bot + ((chunk - 1) * 16 + bk) * 256 + c0 + bc);
    *(float4*)&dst[bk * 128 + bc]     = *(const float4*)Bg;
    *(float4*)&dst[bk * 128 + bc + 4] = *(const float4*)(Bg + 4);
}
__device__ __forceinline__ void ldB_h(float* dst, int chunk,
                                      const float* __restrict__ Wlh_bot,
                                      int bk, int bc) {
    const float* Bg = (chunk == 0)
        ? (g_Bh_top + bk * 128 + bc)
        : (Wlh_bot + ((size_t)((chunk - 1) * 16 + bk)) * 128 + bc);
    *(float4*)&dst[bk * 128 + bc]     = *(const float4*)Bg;
    *(float4*)&dst[bk * 128 + bc + 4] = *(const float4*)(Bg + 4);
}

#define GEMM_CHUNK(Abase, astride, BsBuf)                                   \
    _Pragma("unroll")                                                       \
    for (int kk = 0; kk < 16; ++kk) {                                       \
        float ra[8];                                                        \
        *(float4*)ra       = *(const float4*)&(Abase)[kk * (astride) + ty * 8];     \
        *(float4*)(ra + 4) = *(const float4*)&(Abase)[kk * (astride) + ty * 8 + 4]; \
        ulonglong2 b01 = *(const ulonglong2*)&(BsBuf)[kk * 128 + tx * 8];   \
        ulonglong2 b23 = *(const ulonglong2*)&(BsBuf)[kk * 128 + tx * 8 + 4];\
        unsigned long long rb0 = b01.x, rb1 = b01.y, rb2 = b23.x, rb3 = b23.y;\
        _Pragma("unroll")                                                   \
        for (int i = 0; i < 8; ++i) {                                       \
            unsigned long long rap = pack2(ra[i], ra[i]);                   \
            fma2(accp[i][0], rap, rb0);                                     \
            fma2(accp[i][1], rap, rb1);                                     \
            fma2(accp[i][2], rap, rb2);                                     \
            fma2(accp[i][3], rap, rb3);                                     \
        }                                                                   \
    }

#define ACC_RESET()                                                         \
    _Pragma("unroll") for (int i = 0; i < 8; ++i)                           \
    _Pragma("unroll") for (int j = 0; j < 4; ++j) accp[i][j] = 0ull;

__global__ __launch_bounds__(256) void k_cell(const float* __restrict__ agg,
                                              int t, int mode,
                                              const float* __restrict__ Wlh_bot) {
    extern __shared__ __align__(16) float sm[];
    float* As  = sm;                      // [144][128], k-major (row k, col m)
    float* hrs = As + 144 * 128;          // [128][HRS]  hr, k-major
    float* zs  = hrs + 128 * HRS;         // [128][128]  z, row-major [m][c]
    float* Bs  = zs + 128 * 128;          // [2][16][128]

    int tid = threadIdx.x;
    int n0 = blockIdx.x * 128;
    const float* hsrc = mode ? g_hw : g_h;
    const unsigned char* me = g_meff + (size_t)t * NN;
    const unsigned char* mk = g_maskc + (size_t)t * NN;

    int ty = tid >> 4, tx = tid & 15;
    int lr = tid >> 1, lq = tid & 1;
    int bk = tid >> 4, bc = (tid & 15) * 8;

    int nA = n0 + lr;
    bool rowValid = (nA < NN);
    bool rowOn = rowValid && (mode ? true : (me[nA] != 0));

    // ---- stage A = [agg(16) | h_eff(128)] transposed, and prefetch B z-chunk0 ----
    ldB_zr(Bs, 0, 0, bk, bc);
#pragma unroll
    for (int h2 = 0; h2 < 2; ++h2) {
        int kq = lq + 2 * h2;
        float4 v = make_float4(0.f, 0.f, 0.f, 0.f);
        if (rowValid) v = *(const float4*)(agg + (size_t)nA * 16 + 4 * kq);
        As[(4 * kq + 0) * 128 + lr] = v.x;
        As[(4 * kq + 1) * 128 + lr] = v.y;
        As[(4 * kq + 2) * 128 + lr] = v.z;
        As[(4 * kq + 3) * 128 + lr] = v.w;
    }
#pragma unroll
    for (int g = 0; g < 8; ++g) {
#pragma unroll
        for (int h2 = 0; h2 < 2; ++h2) {
            int kq = lq + 2 * h2;
            float4 v = make_float4(0.f, 0.f, 0.f, 0.f);
            if (rowOn) v = *(const float4*)(hsrc + (size_t)nA * HH + g * 16 + 4 * kq);
            int kr = 16 + g * 16 + 4 * kq;
            As[(kr + 0) * 128 + lr] = v.x;
            As[(kr + 1) * 128 + lr] = v.y;
            As[(kr + 2) * 128 + lr] = v.z;
            As[(kr + 3) * 128 + lr] = v.w;
        }
    }
    __syncthreads();

    unsigned long long accp[8][4];

    // ================= phase Z =================
    ACC_RESET();
    for (int chunk = 0; chunk < 9; ++chunk) {
        float* cur = Bs + (chunk & 1) * 2048;
        if (chunk < 8) ldB_zr(Bs + ((chunk + 1) & 1) * 2048, chunk + 1, 0, bk, bc);
        GEMM_CHUNK(As + chunk * 16 * 128, 128, cur);
        __syncthreads();
    }
    // epilogue: z -> zs (same-thread reuse later)
#pragma unroll
    for (int i = 0; i < 8; ++i) {
        int ml = ty * 8 + i;
#pragma unroll
        for (int jp = 0; jp < 4; ++jp) {
            float2 v = unpack2(accp[i][jp]);
            int c = tx * 8 + 2 * jp;
            zs[ml * 128 + c]     = sigmoidf_(v.x + g_bzr[c]);
            zs[ml * 128 + c + 1] = sigmoidf_(v.y + g_bzr[c + 1]);
        }
    }

    // ================= phase R =================
    ACC_RESET();
    ldB_zr(Bs, 0, 128, bk, bc);
    __syncthreads();
    for (int chunk = 0; chunk < 9; ++chunk) {
        float* cur = Bs + (chunk & 1) * 2048;
        if (chunk < 8) ldB_zr(Bs + ((chunk + 1) & 1) * 2048, chunk + 1, 128, bk, bc);
        GEMM_CHUNK(As + chunk * 16 * 128, 128, cur);
        __syncthreads();
    }
    // epilogue: hr = h_eff * r  (store k-major into hrs)
#pragma unroll
    for (int i = 0; i < 8; ++i) {
        int ml = ty * 8 + i;
#pragma unroll
        for (int jp = 0; jp < 4; ++jp) {
            float2 v = unpack2(accp[i][jp]);
            int c = tx * 8 + 2 * jp;
            float r0 = sigmoidf_(v.x + g_bzr[128 + c]);
            float r1 = sigmoidf_(v.y + g_bzr[128 + c + 1]);
            float h0 = As[(16 + c) * 128 + ml];
            float h1 = As[(16 + c + 1) * 128 + ml];
            hrs[c * HRS + ml]       = h0 * r0;
            hrs[(c + 1) * HRS + ml] = h1 * r1;
        }
    }

    // ================= phase H =================
    ACC_RESET();
    ldB_h(Bs, 0, Wlh_bot, bk, bc);
    __syncthreads();
    for (int chunk = 0; chunk < 9; ++chunk) {
        float* cur = Bs + (chunk & 1) * 2048;
        if (chunk < 8) ldB_h(Bs + ((chunk + 1) & 1) * 2048, chunk + 1, Wlh_bot, bk, bc);
        if (chunk == 0) {
            GEMM_CHUNK(As, 128, cur);
        } else {
            GEMM_CHUNK(hrs + (chunk - 1) * 16 * HRS, HRS, cur);
        }
        __syncthreads();
    }
    // combine: h_new = z*h_eff + (1-z)*tanh(acc + bh)
#pragma unroll
    for (int i = 0; i < 8; ++i) {
        int ml = ty * 8 + i;
        int n = n0 + ml;
        if (n >= NN) continue;
        bool wr = mode ? true : (mk[n] != 0);
        if (!wr) continue;
        float* hdst = mode ? g_hw : g_h;
#pragma unroll
        for (int jp = 0; jp < 4; ++jp) {
            float2 v = unpack2(accp[i][jp]);
            int c = tx * 8 + 2 * jp;
#pragma unroll
            for (int u = 0; u < 2; ++u) {
                float val = (u == 0) ? v.x : v.y;
                int cc = c + u;
                float ht = tanhf(val + g_bh[cc]);
                float zv = zs[ml * 128 + cc];
                float heff = As[(16 + cc) * 128 + ml];   // already masked at staging
                hdst[(size_t)n * HH + cc] = zv * heff + (1.f - zv) * ht;
            }
        }
    }
}

// ---------------- transition / horizon helpers ----------------
__global__ void k_transition(const float* __restrict__ agg11) {
    int i = blockIdx.x * blockDim.x + threadIdx.x;
    if (i < NN * HH) {
        int n = i >> 7;
        g_hw[i] = g_maskc[11 * NN + n] ? g_h[i] : 0.f;
    }
    if (i < NN * FF) g_aggh[i] = agg11[i];
}

__global__ void k_aggh_init3(const float* __restrict__ pred) {
    int i = blockIdx.x * blockDim.x + threadIdx.x;
    if (i >= NN * OUTD) return;
    int n = i / 3, c = i - n * 3;
    float di = g_dinv_all[11 * NN + n];
    g_aggh[n * FF + c] = di * di * pred[i];
}

__global__ void k_scatter3(const int* __restrict__ ei11,
                           const float* __restrict__ pred) {
    int e = blockIdx.x * blockDim.x + threadIdx.x;
    if (e >= EE) return;
    int s = ei11[e], d = ei11[EE + e];
    float nrm = g_nrm11[e];
    float p0 = pred[s * 3 + 0], p1 = pred[s * 3 + 1], p2 = pred[s * 3 + 2];
    float* o = g_aggh + (size_t)d * FF;
    REDV2(o, nrm * p0, nrm * p1);
    RED1(o + 2, nrm * p2);
}

__global__ void k_pred(float* __restrict__ outk, const float* __restrict__ W,
                       const float* __restrict__ b) {
    int gt = blockIdx.x * blockDim.x + threadIdx.x;
    int warp = gt >> 5, lane = gt & 31;
    if (warp >= NN) return;
    const float* h = g_hw + (size_t)warp * HH;
    float p0 = 0.f, p1 = 0.f, p2 = 0.f;
#pragma unroll
    for (int i = 0; i < 4; ++i) {
        int c = lane + 32 * i;
        float hv = h[c];
        const float* w = W + c * 3;
        p0 += hv * w[0]; p1 += hv * w[1]; p2 += hv * w[2];
    }
#pragma unroll
    for (int o = 16; o > 0; o >>= 1) {
        p0 += __shfl_xor_sync(0xFFFFFFFFu, p0, o);
        p1 += __shfl_xor_sync(0xFFFFFFFFu, p1, o);
        p2 += __shfl_xor_sync(0xFFFFFFFFu, p2, o);
    }
    if (lane == 0) {
        outk[warp * 3 + 0] = p0 + b[0];
        outk[warp * 3 + 1] = p1 + b[1];
        outk[warp * 3 + 2] = p2 + b[2];
    }
}

// ---------------- launch ----------------
extern "C" void kernel_launch(void* const* d_in, const int* in_sizes, int n_in,
                              void* d_out, int out_size) {
    const float* x_seq = (const float*)d_in[0];
    const int*   ei    = (const int*)d_in[1];
    const float* ea    = (const float*)d_in[2];
    const unsigned char* mraw = (const unsigned char*)d_in[3];
    const float* Wcz = (const float*)d_in[4];
    const float* bcz = (const float*)d_in[5];
    const float* Wlz = (const float*)d_in[6];
    const float* blz = (const float*)d_in[7];
    const float* Wcr = (const float*)d_in[8];
    const float* bcr = (const float*)d_in[9];
    const float* Wlr = (const float*)d_in[10];
    const float* blr = (const float*)d_in[11];
    const float* Wch = (const float*)d_in[12];
    const float* bch = (const float*)d_in[13];
    const float* Wlh = (const float*)d_in[14];
    const float* blh = (const float*)d_in[15];
    const float* hW  = (const float*)d_in[16];
    const float* hb  = (const float*)d_in[17];
    float* out = (float*)d_out;

    void* p;
    cudaGetSymbolAddress(&p, g_agg_all);
    const float* agg_all = (const float*)p;
    cudaGetSymbolAddress(&p, g_aggh);
    const float* aggh = (const float*)p;

    static int s_attr_done = 0;
    if (!s_attr_done) {
        cudaFuncSetAttribute(k_cell, cudaFuncAttributeMaxDynamicSharedMemorySize,
                             SMEM_CELL);
        s_attr_done = 1;
    }

    const int THR = 256;

    k_detect<<<1, THR>>>(mraw);
    k_convert<<<(NN + THR - 1) / THR, THR>>>(mraw);
    k_fuse<<<(6528 + 128 * 256 + THR - 1) / THR, THR>>>(Wcz, Wlz, blz, bcz,
                                                        Wcr, Wlr, blr, bcr,
                                                        Wch, Wlh, blh, bch);
    k_init<<<(NN * HH + THR - 1) / THR, THR>>>();
    k_deg_all<<<(TT * EE + THR - 1) / THR, THR>>>(ei, ea);
    k_dinv_fin<<<(TT * NN + THR - 1) / THR, THR>>>();
    k_aggself_all<<<(TT * NN + THR - 1) / THR, THR>>>(x_seq);
    k_scatter_all<<<(TT * EE + THR - 1) / THR, THR>>>(ei, ea, x_seq);

    dim3 gC((NN + 127) / 128);
    const float* Wlh_bot = Wlh + 128 * 128;

    for (int t = 0; t < TT; ++t) {
        const float* aggt = agg_all + (size_t)t * NN * FF;
        k_cell<<<gC, THR, SMEM_CELL>>>(aggt, t, 0, Wlh_bot);
    }

    const float* agg11 = agg_all + (size_t)11 * NN * FF;
    k_transition<<<(NN * HH + THR - 1) / THR, THR>>>(agg11);

    const int* eiL = ei + (size_t)11 * 2 * EE;

    for (int k = 0; k < HOR; ++k) {
        const float* aggk = agg11;
        if (k > 0) {
            const float* predPrev = out + (size_t)(k - 1) * NN * OUTD;
            k_aggh_init3<<<(NN * OUTD + THR - 1) / THR, THR>>>(predPrev);
            k_scatter3<<<(EE + THR - 1) / THR, THR>>>(eiL, predPrev);
            aggk = aggh;
        }
        k_cell<<<gC, THR, SMEM_CELL>>>(aggk, 11, 1, Wlh_bot);
        k_pred<<<(NN * 32 + THR - 1) / THR, THR>>>(out + (size_t)k * NN * OUTD, hW, hb);
    }
}